// round 2
// baseline (speedup 1.0000x reference)
#include <cuda_runtime.h>

#define NG 1024
#define R0 8192
#define C0 4096
#define R1 4096
#define C1 2048
#define RM 512

// Scratch (device globals — no allocation allowed)
__device__ int    g_counts[NG];
__device__ int    g_off[NG + 1];
__device__ int    g_cursor[NG];
__device__ int    g_rows[R0];
__device__ float  g_p2[C0];
__device__ float  g_p1[R1];
__device__ double g_loss[3];
__device__ int    g_is64;

__device__ __forceinline__ int load_idx(const void* idx, int i) {
    if (g_is64) return (int)(((const long long*)idx)[i]);
    return ((const int*)idx)[i];
}

__device__ __forceinline__ float block_reduce256(float v, float* sh) {
    int t = threadIdx.x;
    #pragma unroll
    for (int o = 16; o; o >>= 1) v += __shfl_down_sync(0xffffffffu, v, o);
    if ((t & 31) == 0) sh[t >> 5] = v;
    __syncthreads();
    if (t < 8) {
        v = sh[t];
        #pragma unroll
        for (int o = 4; o; o >>= 1) v += __shfl_down_sync(0x000000ffu, v, o);
    }
    return v; // valid in thread 0
}

__global__ void k_zero() {
    int i = blockIdx.x * blockDim.x + threadIdx.x;
    if (i < C0) g_p2[i] = 0.f;
    if (i < NG) g_counts[i] = 0;
    if (i < 3)  g_loss[i] = 0.0;
    if (i == 0) g_is64 = 1;
}

// Detect idx0 element width: if data is int64 (little-endian, 0<=v<1024),
// every odd 32-bit word of the buffer is 0. If int32, odd words are random
// group ids (all-zero probability ~0). Reads 32KB, valid for either width.
__global__ void k_detect(const unsigned int* __restrict__ idx_raw) {
    int i = blockIdx.x * blockDim.x + threadIdx.x;
    if (i < R0 / 2) {
        if (idx_raw[2 * i + 1] != 0u) atomicExch(&g_is64, 0);
    }
}

__global__ void k_count(const void* __restrict__ idx) {
    int i = blockIdx.x * blockDim.x + threadIdx.x;
    if (i < R0) atomicAdd(&g_counts[load_idx(idx, i)], 1);
}

__global__ void k_scan() {   // one block, 1024 threads
    __shared__ int sh[NG];
    int t = threadIdx.x;
    int mine = g_counts[t];
    sh[t] = mine;
    __syncthreads();
    for (int d = 1; d < NG; d <<= 1) {
        int v = (t >= d) ? sh[t - d] : 0;
        __syncthreads();
        sh[t] += v;
        __syncthreads();
    }
    int excl = sh[t] - mine;
    g_off[t] = excl;
    g_cursor[t] = excl;
    if (t == NG - 1) g_off[NG] = sh[t];
}

__global__ void k_fill(const void* __restrict__ idx) {
    int i = blockIdx.x * blockDim.x + threadIdx.x;
    if (i < R0) {
        int g = load_idx(idx, i);
        int p = atomicAdd(&g_cursor[g], 1);
        g_rows[p] = i;
    }
}

// Fused obs-A + p2 accumulation.
// Grid: (C0/1024, NG). Block = 256 threads, 4 floats/thread (float4).
// Each block owns one (group, 1024-column tile): registers hold the segment
// sum, loss_a squared-diff computed in place (s0 never materialized), and the
// per-column partial folds into g_p2 with one float atomic per column.
__global__ void k_obsA(const float* __restrict__ theta0, const float* __restrict__ obs0) {
    __shared__ float sh[8];
    int g = blockIdx.y;
    int c = (blockIdx.x * blockDim.x + threadIdx.x) * 4;
    int base = __ldg(&g_off[g]);
    int cnt  = __ldg(&g_off[g + 1]) - base;
    float ax = 0.f, ay = 0.f, az = 0.f, aw = 0.f;
    for (int j = 0; j < cnt; j++) {
        int r = __ldg(&g_rows[base + j]);
        float4 v = *(const float4*)(theta0 + (size_t)r * C0 + c);
        ax += __expf(v.x); ay += __expf(v.y);
        az += __expf(v.z); aw += __expf(v.w);
    }
    atomicAdd(&g_p2[c + 0], ax);
    atomicAdd(&g_p2[c + 1], ay);
    atomicAdd(&g_p2[c + 2], az);
    atomicAdd(&g_p2[c + 3], aw);
    float4 o = *(const float4*)(obs0 + (size_t)g * C0 + c);
    float dx = o.x - ax, dy = o.y - ay, dz = o.z - az, dw = o.w - aw;
    float v = dx * dx + dy * dy + dz * dz + dw * dw;
    v = block_reduce256(v, sh);
    if (threadIdx.x == 0) atomicAdd(&g_loss[0], (double)v);
}

__global__ void k_obsC(const float* __restrict__ obs2) {
    __shared__ float sh[8];
    int c = blockIdx.x * blockDim.x + threadIdx.x;
    float d = obs2[c] - g_p2[c];
    float v = block_reduce256(d * d, sh);
    if (threadIdx.x == 0) atomicAdd(&g_loss[2], (double)v);
}

// Row-sum of exp(theta1): one warp per row, float4 loads.
__global__ void k_p1(const float* __restrict__ theta1) {
    int gid = blockIdx.x * blockDim.x + threadIdx.x;
    int w = gid >> 5, lane = gid & 31;
    const float4* row = (const float4*)(theta1 + (size_t)w * C1);
    float s = 0.f;
    #pragma unroll 4
    for (int j = lane; j < C1 / 4; j += 32) {
        float4 v = row[j];
        s += __expf(v.x) + __expf(v.y) + __expf(v.z) + __expf(v.w);
    }
    #pragma unroll
    for (int o = 16; o; o >>= 1) s += __shfl_down_sync(0xffffffffu, s, o);
    if (lane == 0) g_p1[w] = s;
}

// mapping1 @ p1 + loss_b: one warp per output row. p1 (16KB) hits L1/L2.
__global__ void k_obsB(const float* __restrict__ mapping1, const float* __restrict__ obs1) {
    int gid = blockIdx.x * blockDim.x + threadIdx.x;
    int w = gid >> 5, lane = gid & 31;
    const float4* row = (const float4*)(mapping1 + (size_t)w * C0);
    const float4* p = (const float4*)g_p1;
    float s = 0.f;
    #pragma unroll 4
    for (int j = lane; j < C0 / 4; j += 32) {
        float4 m = row[j];
        float4 q = p[j];
        s += m.x * q.x + m.y * q.y + m.z * q.z + m.w * q.w;
    }
    #pragma unroll
    for (int o = 16; o; o >>= 1) s += __shfl_down_sync(0xffffffffu, s, o);
    if (lane == 0) {
        double d = (double)obs1[w] - (double)s;
        atomicAdd(&g_loss[1], d * d);
    }
}

__global__ void k_final(float* out) {
    double la = g_loss[0] / (double)((size_t)NG * (size_t)C0);
    double lb = g_loss[1] / (double)RM;
    double lc = 0.5 * g_loss[2] / (double)C0;
    out[0] = (float)((la + lb + lc) / 3.0);
}

extern "C" void kernel_launch(void* const* d_in, const int* in_sizes, int n_in,
                              void* d_out, int out_size) {
    const float* theta0   = (const float*)d_in[0];
    const float* theta1   = (const float*)d_in[1];
    const float* obs0     = (const float*)d_in[2];
    const float* obs1     = (const float*)d_in[3];
    const float* obs2     = (const float*)d_in[4];
    const void*  idx0     = d_in[5];
    const float* mapping1 = (const float*)d_in[6];
    float* out = (float*)d_out;

    k_zero<<<16, 256>>>();
    k_detect<<<16, 256>>>((const unsigned int*)idx0);
    k_count<<<32, 256>>>(idx0);
    k_scan<<<1, 1024>>>();
    k_fill<<<32, 256>>>(idx0);

    dim3 gA(C0 / 1024, NG);
    k_obsA<<<gA, 256>>>(theta0, obs0);
    k_obsC<<<16, 256>>>(obs2);

    k_p1<<<(R1 * 32) / 256, 256>>>(theta1);
    k_obsB<<<(RM * 32) / 256, 256>>>(mapping1, obs1);

    k_final<<<1, 1>>>(out);
}